// round 1
// baseline (speedup 1.0000x reference)
#include <cuda_runtime.h>

#define SE 12288           // S*E = 1024*12
#define EPSF 1e-5f

static __device__ float g_attn[1024 * 12];
static __device__ float g_ffn [1024 * 12];

// ---------------------------------------------------------------------------
// Prep: attn[b,:] and ffn[b,:] for all b in [0,1024).
//   z_i     = cos(x[b,i,0]) * cos(rx_i)
//   attn[b,0] = prod_{i=1..11} z_i ;  attn[b,w] = prod_{i=0..w} z_i (w>=1)
//   tok2_i  = LN1(x[b,i,:] + attn[i,:])[0]
//   ffn[b,e]= b_ffn[e] + sum_i relu(cos(tok2_i + ry_i)) * w_ffn[e,i]
// 8 blocks x 128 threads, one thread per b.
// ---------------------------------------------------------------------------
__global__ void prep_kernel(const float* __restrict__ x,
                            const float* __restrict__ rx,
                            const float* __restrict__ ry,
                            const float* __restrict__ w_ffn,
                            const float* __restrict__ b_ffn,
                            const float* __restrict__ ln1_g,
                            const float* __restrict__ ln1_b)
{
    __shared__ float attn_loc[12][12];
    const int b = blockIdx.x * blockDim.x + threadIdx.x;

    float cosrx[12];
#pragma unroll
    for (int i = 0; i < 12; i++) cosrx[i] = cosf(__ldg(&rx[i]));

    // attn rows 0..11 (needed by every thread's ffn) -> shared, per block
    if (threadIdx.x < 12) {
        const int i = threadIdx.x;
        float z[12];
#pragma unroll
        for (int k = 0; k < 12; k++)
            z[k] = cosf(__ldg(&x[i * SE + k * 12])) * cosrx[k];
        float q = 1.f;
#pragma unroll
        for (int k = 1; k < 12; k++) q *= z[k];
        attn_loc[i][0] = q;
        float p = z[0];
#pragma unroll
        for (int w = 1; w < 12; w++) { p *= z[w]; attn_loc[i][w] = p; }
    }
    __syncthreads();

    // attn for own b
    {
        float z[12];
#pragma unroll
        for (int k = 0; k < 12; k++)
            z[k] = cosf(__ldg(&x[(size_t)b * SE + k * 12])) * cosrx[k];
        float q = 1.f;
#pragma unroll
        for (int k = 1; k < 12; k++) q *= z[k];
        g_attn[b * 12 + 0] = q;
        float p = z[0];
#pragma unroll
        for (int w = 1; w < 12; w++) { p *= z[w]; g_attn[b * 12 + w] = p; }
    }

    // ffn for own b
    const float g10 = __ldg(&ln1_g[0]);
    const float b10 = __ldg(&ln1_b[0]);
    float r[12];
#pragma unroll
    for (int i = 0; i < 12; i++) {
        const float4* row = (const float4*)(x + (size_t)b * SE + i * 12);
        float4 a0 = __ldg(row), a1 = __ldg(row + 1), a2 = __ldg(row + 2);
        float y[12] = {a0.x, a0.y, a0.z, a0.w,
                       a1.x, a1.y, a1.z, a1.w,
                       a2.x, a2.y, a2.z, a2.w};
        float sum = 0.f;
#pragma unroll
        for (int e = 0; e < 12; e++) { y[e] += attn_loc[i][e]; sum += y[e]; }
        const float mu = sum * (1.f / 12.f);
        float sq = 0.f;
#pragma unroll
        for (int e = 0; e < 12; e++) { const float d = y[e] - mu; sq += d * d; }
        const float rs  = rsqrtf(sq * (1.f / 12.f) + EPSF);
        const float x10 = (y[0] - mu) * rs * g10 + b10;
        r[i] = fmaxf(cosf(x10 + __ldg(&ry[i])), 0.f);
    }
#pragma unroll
    for (int e = 0; e < 12; e++) {
        float acc = __ldg(&b_ffn[e]);
#pragma unroll
        for (int i = 0; i < 12; i++)
            acc = fmaf(r[i], __ldg(&w_ffn[e * 12 + i]), acc);
        g_ffn[b * 12 + e] = acc;
    }
}

// ---------------------------------------------------------------------------
// Main: out[b,s,:] = LN2( LN1(x[b,s,:] + attn[s,:]) + ffn[s,:] )
// Block = 256 threads covering a (S_TILE=64) x (B_TILE=32) tile of rows.
// Thread = (s_idx = tid&63, b_grp = tid>>6); processes 8 consecutive b for a
// fixed s -> attn/ffn/ln tables stay in registers (8x reuse), loads/stores
// stay coalesced along s (warp = 32 consecutive 48B rows = 1536B contig).
// ---------------------------------------------------------------------------
__global__ __launch_bounds__(256) void main_kernel(
    const float* __restrict__ x, float* __restrict__ out,
    const float* __restrict__ ln1_g, const float* __restrict__ ln1_b,
    const float* __restrict__ ln2_g, const float* __restrict__ ln2_b)
{
    const int s_idx = threadIdx.x & 63;
    const int b_grp = threadIdx.x >> 6;          // 0..3
    const int s     = blockIdx.x * 64 + s_idx;
    const int b0    = blockIdx.y * 32 + b_grp * 8;

    float attn_s[12], g1[12], c1[12], g2[12], b2[12];
#pragma unroll
    for (int e = 0; e < 12; e++) {
        attn_s[e] = g_attn[s * 12 + e];
        g1[e] = __ldg(&ln1_g[e]);
        c1[e] = __ldg(&ln1_b[e]) + g_ffn[s * 12 + e];   // fold ffn into LN1 bias
        g2[e] = __ldg(&ln2_g[e]);
        b2[e] = __ldg(&ln2_b[e]);
    }

#pragma unroll
    for (int bi = 0; bi < 8; bi++) {
        const size_t off = ((size_t)(b0 + bi) * 1024 + (size_t)s) * 12;
        const float4* row = (const float4*)(x + off);
        float4 a0 = __ldg(row), a1 = __ldg(row + 1), a2 = __ldg(row + 2);
        float y[12] = {a0.x, a0.y, a0.z, a0.w,
                       a1.x, a1.y, a1.z, a1.w,
                       a2.x, a2.y, a2.z, a2.w};
        float sum = 0.f;
#pragma unroll
        for (int e = 0; e < 12; e++) { y[e] += attn_s[e]; sum += y[e]; }
        const float mu = sum * (1.f / 12.f);
        float sq = 0.f;
#pragma unroll
        for (int e = 0; e < 12; e++) { const float d = y[e] - mu; sq += d * d; }
        const float rs1 = rsqrtf(sq * (1.f / 12.f) + EPSF);

        float y2[12];
        float sum2 = 0.f;
#pragma unroll
        for (int e = 0; e < 12; e++) {
            y2[e] = (y[e] - mu) * rs1 * g1[e] + c1[e];
            sum2 += y2[e];
        }
        const float mu2 = sum2 * (1.f / 12.f);
        float sq2 = 0.f;
#pragma unroll
        for (int e = 0; e < 12; e++) { const float d = y2[e] - mu2; sq2 += d * d; }
        const float rs2 = rsqrtf(sq2 * (1.f / 12.f) + EPSF);

        float o[12];
#pragma unroll
        for (int e = 0; e < 12; e++)
            o[e] = (y2[e] - mu2) * rs2 * g2[e] + b2[e];

        float4* orow = (float4*)(out + off);
        orow[0] = make_float4(o[0], o[1], o[2],  o[3]);
        orow[1] = make_float4(o[4], o[5], o[6],  o[7]);
        orow[2] = make_float4(o[8], o[9], o[10], o[11]);
    }
}

extern "C" void kernel_launch(void* const* d_in, const int* in_sizes, int n_in,
                              void* d_out, int out_size)
{
    const float* x     = (const float*)d_in[0];
    const float* rx    = (const float*)d_in[1];
    const float* ry    = (const float*)d_in[2];
    const float* w_ffn = (const float*)d_in[3];
    const float* b_ffn = (const float*)d_in[4];
    const float* ln1_g = (const float*)d_in[5];
    const float* ln1_b = (const float*)d_in[6];
    const float* ln2_g = (const float*)d_in[7];
    const float* ln2_b = (const float*)d_in[8];
    float* out = (float*)d_out;

    prep_kernel<<<8, 128>>>(x, rx, ry, w_ffn, b_ffn, ln1_g, ln1_b);

    dim3 grid(16, 32);   // 16 s-tiles x 32 b-tiles = 512 blocks
    main_kernel<<<grid, 256>>>(x, out, ln1_g, ln1_b, ln2_g, ln2_b);
}